// round 11
// baseline (speedup 1.0000x reference)
#include <cuda_runtime.h>
#include <cuda_bf16.h>

#define BB   8
#define NN   32768
#define KK   20
#define CHN  16
#define NPTS (BB * 32768)

#define L2E 1.44269504088896f   // log2(e)
#define ZSH 20.0f               // fixed softmax shift (range guard, shift-invariant)

typedef unsigned long long u64;

// ---- f32x2 packed helpers (sm_103a FFMA2 path; ptxas won't emit from C++) ----
__device__ __forceinline__ u64 pk2(float lo, float hi) {
    u64 r; asm("mov.b64 %0, {%1, %2};" : "=l"(r) : "f"(lo), "f"(hi)); return r;
}
__device__ __forceinline__ void upk2(u64 v, float& lo, float& hi) {
    asm("mov.b64 {%0, %1}, %2;" : "=f"(lo), "=f"(hi) : "l"(v));
}
__device__ __forceinline__ u64 fma2(u64 a, u64 b, u64 c) {
    u64 r; asm("fma.rn.f32x2 %0, %1, %2, %3;" : "=l"(r) : "l"(a), "l"(b), "l"(c)); return r;
}
__device__ __forceinline__ u64 mul2(u64 a, u64 b) {
    u64 r; asm("mul.rn.f32x2 %0, %1, %2;" : "=l"(r) : "l"(a), "l"(b)); return r;
}
__device__ __forceinline__ u64 abs2(u64 a) {
    u64 r; asm("and.b64 %0, %1, 0x7FFFFFFF7FFFFFFF;" : "=l"(r) : "l"(a)); return r;
}

// 8 lanes per point: lane = (hi, q). Iteration kp: hi=0 -> k=2kp, hi=1 -> k=2kp+1;
// q = channel quarter. Coop gather (R9): lane l8 loads k = l8, l8+8, l8+16(<20),
// broadcast by shfl. Channel math in packed f32x2; each lane's packed pair is
// exactly its 16B store chunk -> warp STG.128 covers 4 FULL 128B lines.
__global__ void __launch_bounds__(128, 10)
gap_kernel(const float* __restrict__ x,
           const int*   __restrict__ idx32,
           const float* __restrict__ w1,  const float* __restrict__ g1,
           const float* __restrict__ b1,  const float* __restrict__ m1,
           const float* __restrict__ v1,
           const float* __restrict__ w2,  const float* __restrict__ g2,
           const float* __restrict__ b2,  const float* __restrict__ m2,
           const float* __restrict__ v2,
           const float* __restrict__ w1n, const float* __restrict__ g1n,
           const float* __restrict__ b1n, const float* __restrict__ m1n,
           const float* __restrict__ v1n,
           const float* __restrict__ w2n, const float* __restrict__ g2n,
           const float* __restrict__ b2n, const float* __restrict__ m2n,
           const float* __restrict__ v2n,
           float* __restrict__ out, float* __restrict__ edge_o)
{
    // ---- fold BN into affine constants ----
    __shared__ float sA1[CHN], sB1[CHN], sC1[CHN], sW2[CHN];
    __shared__ float sAn[CHN], sBn[CHN], sCn[CHN], sWn[CHN];
    __shared__ float sZC;

    int t = threadIdx.x;
    if (t < CHN) {
        float s1 = g1[t] * rsqrtf(v1[t] + 1e-5f);
        sA1[t] = w1[2*t]     * s1;
        sB1[t] = w1[2*t + 1] * s1;
        sC1[t] = b1[t] - m1[t] * s1;
        float s2 = g2[0] * rsqrtf(v2[0] + 1e-5f);
        sW2[t] = w2[t] * s2;

        float s1n = g1n[t] * rsqrtf(v1n[t] + 1e-5f);
        sAn[t] = w1n[2*t]     * s1n;
        sBn[t] = w1n[2*t + 1] * s1n;
        sCn[t] = b1n[t] - m1n[t] * s1n;
        float s2n = g2n[0] * rsqrtf(v2n[0] + 1e-5f);
        sWn[t] = w2n[t] * s2n;

        if (t == 0) {
            float c2  = b2[0]  - m2[0]  * (g2[0]  * rsqrtf(v2[0]  + 1e-5f));
            float c2n = b2n[0] - m2n[0] * (g2n[0] * rsqrtf(v2n[0] + 1e-5f));
            sZC = c2 + c2n;
        }
    }

    // ---- merged idx-width detect: odd 32-bit words of first 64 int64 elems ----
    // all zero <=> little-endian int64 (values < 2^15). Barrier doubles as the
    // smem-weight sync.
    unsigned int oddw = 0;
    if (t < 64) oddw = ((const unsigned int*)idx32)[2 * t + 1];
    int sh = __syncthreads_or(oddw != 0) ? 0 : 1;   // 1 -> int64 idx

    int g   = blockIdx.x * 128 + t;
    int p   = g >> 3;                   // point id (8 lanes per point)
    int l8  = t & 7;                    // lane within 8-lane point group
    int q   = t & 3;                    // channel quarter
    int hi  = (t >> 2) & 1;             // k parity handled by this lane
    int c0  = q << 2;
    int b   = p >> 15;                  // N = 2^15
    int n   = p & 32767;
    int gb  = (t & 31) & 24;            // group base lane (for shfl source)

    const float* xrow = x + b * NN;
    float xc = __ldg(xrow + n);

    // packed per-thread folded constants for this quarter's 4 channels
    u64 A1p[2], D1p[2], Anp[2], Dnp[2], W2p[2], Wnp[2];
#pragma unroll
    for (int i = 0; i < 2; i++) {
        int cc = c0 + 2 * i;
        A1p[i] = pk2(sA1[cc], sA1[cc+1]);
        D1p[i] = pk2(fmaf(sB1[cc],   xc, sC1[cc]),  fmaf(sB1[cc+1], xc, sC1[cc+1]));
        Anp[i] = pk2(sAn[cc], sAn[cc+1]);
        Dnp[i] = pk2(fmaf(sBn[cc],   xc, sCn[cc]),  fmaf(sBn[cc+1], xc, sCn[cc+1]));
        W2p[i] = pk2(sW2[cc], sW2[cc+1]);
        Wnp[i] = pk2(sWn[cc], sWn[cc+1]);
    }
    float zc = sZC;
    const u64 C04 = pk2(0.4f, 0.4f);
    const u64 C06 = pk2(0.6f, 0.6f);

    // ---- cooperative gather: lane l8 loads k = l8, l8+8, (l8+16 if l8<4) ----
    float xr[3];
    {
        int i0, i1, i2 = 0;
        if (sh) {                       // int64: word index 2*(20p + k)
            const int* ipb = idx32 + (size_t)p * (2 * KK) + 2 * l8;
            i0 = __ldg(ipb + 0);
            i1 = __ldg(ipb + 16);
            if (l8 < 4) i2 = __ldg(ipb + 32);
        } else {                        // int32
            const int* ipb = idx32 + (size_t)p * KK + l8;
            i0 = __ldg(ipb + 0);
            i1 = __ldg(ipb + 8);
            if (l8 < 4) i2 = __ldg(ipb + 16);
        }
        xr[0] = __ldg(xrow + i0);
        xr[1] = __ldg(xrow + i1);
        xr[2] = __ldg(xrow + (l8 < 4 ? i2 : 0));
    }

    u64 accp[2] = {0ull, 0ull};
    float ssum = 0.0f;

    float* ep = edge_o + (size_t)p * (KK * CHN);   // this point's 1280B block

#pragma unroll
    for (int kp = 0; kp < KK / 2; kp++) {
        int klane = 2 * kp + hi;        // this lane's k
        float xvk = __shfl_sync(0xffffffffu, xr[kp >> 2], gb | (klane & 7));
        float d = xvk - xc;
        u64 dd = pk2(d, d);

        u64 sp = 0ull;                  // packed logit partials (+0, +0)
        u64 eop[2];
#pragma unroll
        for (int i = 0; i < 2; i++) {
            u64 t1 = fma2(A1p[i], dd, D1p[i]);
            t1 = fma2(C04, abs2(t1), mul2(C06, t1));   // lrelu = 0.6t + 0.4|t|
            sp = fma2(W2p[i], t1, sp);
            u64 tn = fma2(Anp[i], dd, Dnp[i]);
            tn = fma2(C04, abs2(tn), mul2(C06, tn));
            eop[i] = tn;
            sp = fma2(Wnp[i], tn, sp);
        }
        float slo, shi2; upk2(sp, slo, shi2);
        float s = slo + shi2;
        // reduce the 4 quarters' partial logits
        s += __shfl_xor_sync(0xffffffffu, s, 1);
        s += __shfl_xor_sync(0xffffffffu, s, 2);
        float z = zc + s;
        z = fmaxf(z, 0.2f * z);                 // lrelu(a+e)

        // fixed-shift softmax numerator
        float pkv = exp2f(fmaf(z, L2E, -(ZSH * L2E)));
        ssum += pkv;
        u64 pkp = pk2(pkv, pkv);
        accp[0] = fma2(pkp, eop[0], accp[0]);
        accp[1] = fma2(pkp, eop[1], accp[1]);

        // coalesced streaming store: warp covers 4 points x 128B FULL lines
        float* dst = ep + kp * 32 + l8 * 4;
        asm volatile("st.global.cs.v2.b64 [%0], {%1, %2};"
                     :: "l"(dst), "l"(eop[0]), "l"(eop[1]) : "memory");
    }

    // ---- combine the two k-parity halves (lane l <-> l^4) ----
    float a0, a1, a2, a3;
    upk2(accp[0], a0, a1);
    upk2(accp[1], a2, a3);
    ssum += __shfl_xor_sync(0xffffffffu, ssum, 4);
    a0 += __shfl_xor_sync(0xffffffffu, a0, 4);
    a1 += __shfl_xor_sync(0xffffffffu, a1, 4);
    a2 += __shfl_xor_sync(0xffffffffu, a2, 4);
    a3 += __shfl_xor_sync(0xffffffffu, a3, 4);

    if (hi == 0) {                      // lanes 0-3 of each group write 64B
        float inv = 1.0f / ssum;
        float* op = out + (size_t)p * CHN + c0;
        __stcs((float4*)op, make_float4(a0*inv, a1*inv, a2*inv, a3*inv));
    }
}

extern "C" void kernel_launch(void* const* d_in, const int* in_sizes, int n_in,
                              void* d_out, int out_size) {
    const float* x    = (const float*)d_in[0];
    // d_in[1] = pos (unused), d_in[3] = dis (unused)
    const int*   idx  = (const int*)d_in[2];
    const float* w1   = (const float*)d_in[4];
    const float* g1   = (const float*)d_in[5];
    const float* b1   = (const float*)d_in[6];
    const float* m1   = (const float*)d_in[7];
    const float* v1   = (const float*)d_in[8];
    const float* w2   = (const float*)d_in[9];
    const float* g2   = (const float*)d_in[10];
    const float* b2   = (const float*)d_in[11];
    const float* m2   = (const float*)d_in[12];
    const float* v2   = (const float*)d_in[13];
    const float* w1n  = (const float*)d_in[14];
    const float* g1n  = (const float*)d_in[15];
    const float* b1n  = (const float*)d_in[16];
    const float* m1n  = (const float*)d_in[17];
    const float* v1n  = (const float*)d_in[18];
    const float* w2n  = (const float*)d_in[19];
    const float* g2n  = (const float*)d_in[20];
    const float* b2n  = (const float*)d_in[21];
    const float* m2n  = (const float*)d_in[22];
    const float* v2n  = (const float*)d_in[23];

    float* out  = (float*)d_out;                         // (B,N,CH) first
    float* edge = out + (size_t)NPTS * CHN;              // then (B,N,K,CH)

    // 8 lanes per point: NPTS*8 threads; width-detect merged into the kernel
    gap_kernel<<<(NPTS * 8) / 128, 128>>>(x, idx,
                                    w1, g1, b1, m1, v1, w2, g2, b2, m2, v2,
                                    w1n, g1n, b1n, m1n, v1n, w2n, g2n, b2n, m2n, v2n,
                                    out, edge);
}

// round 12
// speedup vs baseline: 1.0353x; 1.0353x over previous
#include <cuda_runtime.h>
#include <cuda_bf16.h>

#define BB   8
#define NN   32768
#define KK   20
#define CHN  16
#define NPTS (BB * 32768)

#define L2E 1.44269504088896f   // log2(e)
#define ZSH 20.0f               // fixed softmax shift (range guard, shift-invariant)

// 8 lanes per point: lane = (hi, q). Iteration kp: hi=0 -> k=2kp, hi=1 -> k=2kp+1;
// q = channel quarter [4q,4q+4). Coop gather: lane l8 loads k = l8, l8+8,
// (l8+16 if l8<4), broadcast by shfl. Each lane's eo[4] is exactly its 16B
// store chunk -> warp STG.128 covers 4 FULL 128B lines.
// Idx width detection (int64 vs int32) is merged into the kernel: warp 0 of
// each block samples the odd 32-bit words of the first 32 int64 elements; the
// verdict is combined with the weight-fold barrier via __syncthreads_or.
__global__ void __launch_bounds__(128, 10)
gap_kernel(const float* __restrict__ x,
           const int*   __restrict__ idx32,
           const float* __restrict__ w1,  const float* __restrict__ g1,
           const float* __restrict__ b1,  const float* __restrict__ m1,
           const float* __restrict__ v1,
           const float* __restrict__ w2,  const float* __restrict__ g2,
           const float* __restrict__ b2,  const float* __restrict__ m2,
           const float* __restrict__ v2,
           const float* __restrict__ w1n, const float* __restrict__ g1n,
           const float* __restrict__ b1n, const float* __restrict__ m1n,
           const float* __restrict__ v1n,
           const float* __restrict__ w2n, const float* __restrict__ g2n,
           const float* __restrict__ b2n, const float* __restrict__ m2n,
           const float* __restrict__ v2n,
           float* __restrict__ out, float* __restrict__ edge_o)
{
    // ---- fold BN into affine constants ----
    __shared__ float sA1[CHN], sB1[CHN], sC1[CHN], sW2[CHN];
    __shared__ float sAn[CHN], sBn[CHN], sCn[CHN], sWn[CHN];
    __shared__ float sZC;

    int t = threadIdx.x;
    if (t < CHN) {
        float s1 = g1[t] * rsqrtf(v1[t] + 1e-5f);
        sA1[t] = w1[2*t]     * s1;
        sB1[t] = w1[2*t + 1] * s1;
        sC1[t] = b1[t] - m1[t] * s1;
        float s2 = g2[0] * rsqrtf(v2[0] + 1e-5f);
        sW2[t] = w2[t] * s2;

        float s1n = g1n[t] * rsqrtf(v1n[t] + 1e-5f);
        sAn[t] = w1n[2*t]     * s1n;
        sBn[t] = w1n[2*t + 1] * s1n;
        sCn[t] = b1n[t] - m1n[t] * s1n;
        float s2n = g2n[0] * rsqrtf(v2n[0] + 1e-5f);
        sWn[t] = w2n[t] * s2n;

        if (t == 0) {
            float c2  = b2[0]  - m2[0]  * (g2[0]  * rsqrtf(v2[0]  + 1e-5f));
            float c2n = b2n[0] - m2n[0] * (g2n[0] * rsqrtf(v2n[0] + 1e-5f));
            sZC = c2 + c2n;
        }
    }

    // ---- merged idx-width detect (warp 0 only; 256B, L2-broadcast) ----
    // odd words of first 32 little-endian int64 elems all zero <=> int64 idx.
    unsigned int oddw = 0;
    if (t < 32) oddw = ((const unsigned int*)idx32)[2 * t + 1];
    int sh = __syncthreads_or(oddw != 0) ? 0 : 1;   // 1 -> int64 idx

    int g   = blockIdx.x * 128 + t;
    int p   = g >> 3;                   // point id (8 lanes per point)
    int l8  = t & 7;                    // lane within 8-lane point group
    int q   = t & 3;                    // channel quarter
    int hi  = (t >> 2) & 1;             // k parity handled by this lane
    int c0  = q << 2;
    int b   = p >> 15;                  // N = 2^15
    int n   = p & 32767;
    int gb  = (t & 31) & 24;            // group base lane (for shfl source)

    const float* xrow = x + b * NN;
    float xc = __ldg(xrow + n);         // 4 consecutive addrs per warp -> 1 line

    // per-thread folded constants for this quarter's 4 channels
    float A1h[4], D1h[4], Anh[4], Dnh[4], W2h[4], Wnh[4];
#pragma unroll
    for (int c = 0; c < 4; c++) {
        int cc = c0 + c;
        A1h[c] = sA1[cc];
        D1h[c] = fmaf(sB1[cc], xc, sC1[cc]);
        Anh[c] = sAn[cc];
        Dnh[c] = fmaf(sBn[cc], xc, sCn[cc]);
        W2h[c] = sW2[cc];
        Wnh[c] = sWn[cc];
    }
    float zc = sZC;

    // ---- cooperative gather: lane l8 loads k = l8, l8+8, (l8+16 iff l8<4) ----
    float xr[3];
    {
        int i0, i1;
        if (sh) {                       // int64: word index 2*(20p + k)
            const int* ipb = idx32 + (size_t)p * (2 * KK) + 2 * l8;
            i0 = __ldg(ipb + 0);
            i1 = __ldg(ipb + 16);
            if (l8 < 4) {
                int i2 = __ldg(ipb + 32);
                xr[2] = __ldg(xrow + i2);   // only lanes 0-3 issue these
            }
        } else {                        // int32
            const int* ipb = idx32 + (size_t)p * KK + l8;
            i0 = __ldg(ipb + 0);
            i1 = __ldg(ipb + 8);
            if (l8 < 4) {
                int i2 = __ldg(ipb + 16);
                xr[2] = __ldg(xrow + i2);
            }
        }
        xr[0] = __ldg(xrow + i0);
        xr[1] = __ldg(xrow + i1);
    }

    float acc[4];
#pragma unroll
    for (int c = 0; c < 4; c++) acc[c] = 0.0f;
    float ssum = 0.0f;

    float* ep = edge_o + (size_t)p * (KK * CHN);   // this point's 1280B block

#pragma unroll
    for (int kp = 0; kp < KK / 2; kp++) {
        int klane = 2 * kp + hi;        // this lane's k
        // broadcast xv[klane] from the group lane that gathered it
        float xvk = __shfl_sync(0xffffffffu, xr[kp >> 2], gb | (klane & 7));
        float d = xvk - xc;

        float eo[4];
        float s = 0.0f;
#pragma unroll
        for (int c = 0; c < 4; c++) {
            float t1 = fmaf(A1h[c], d, D1h[c]);
            t1 = fmaxf(t1, 0.2f * t1);          // lrelu
            s  = fmaf(W2h[c], t1, s);
            float tn = fmaf(Anh[c], d, Dnh[c]);
            tn = fmaxf(tn, 0.2f * tn);
            eo[c] = tn;
            s  = fmaf(Wnh[c], tn, s);
        }
        // reduce the 4 quarters' partial logits (within the 4-lane k-subgroup)
        s += __shfl_xor_sync(0xffffffffu, s, 1);
        s += __shfl_xor_sync(0xffffffffu, s, 2);
        float z = zc + s;
        z = fmaxf(z, 0.2f * z);                 // lrelu(a+e)

        // fixed-shift softmax numerator
        float pk = exp2f(fmaf(z, L2E, -(ZSH * L2E)));
        ssum += pk;
#pragma unroll
        for (int c = 0; c < 4; c++)
            acc[c] = fmaf(pk, eo[c], acc[c]);

        // coalesced store: warp covers 4 points x 128B FULL lines
        __stcs((float4*)(ep + kp * 32 + l8 * 4), make_float4(eo[0], eo[1], eo[2], eo[3]));
    }

    // ---- combine the two k-parity halves (lane l <-> l^4) ----
    ssum += __shfl_xor_sync(0xffffffffu, ssum, 4);
#pragma unroll
    for (int c = 0; c < 4; c++)
        acc[c] += __shfl_xor_sync(0xffffffffu, acc[c], 4);

    if (hi == 0) {                      // lanes 0-3 of each group write 64B
        float inv = 1.0f / ssum;
        float* op = out + (size_t)p * CHN + c0;
        __stcs((float4*)op, make_float4(acc[0]*inv, acc[1]*inv, acc[2]*inv, acc[3]*inv));
    }
}

extern "C" void kernel_launch(void* const* d_in, const int* in_sizes, int n_in,
                              void* d_out, int out_size) {
    const float* x    = (const float*)d_in[0];
    // d_in[1] = pos (unused), d_in[3] = dis (unused)
    const int*   idx  = (const int*)d_in[2];
    const float* w1   = (const float*)d_in[4];
    const float* g1   = (const float*)d_in[5];
    const float* b1   = (const float*)d_in[6];
    const float* m1   = (const float*)d_in[7];
    const float* v1   = (const float*)d_in[8];
    const float* w2   = (const float*)d_in[9];
    const float* g2   = (const float*)d_in[10];
    const float* b2   = (const float*)d_in[11];
    const float* m2   = (const float*)d_in[12];
    const float* v2   = (const float*)d_in[13];
    const float* w1n  = (const float*)d_in[14];
    const float* g1n  = (const float*)d_in[15];
    const float* b1n  = (const float*)d_in[16];
    const float* m1n  = (const float*)d_in[17];
    const float* v1n  = (const float*)d_in[18];
    const float* w2n  = (const float*)d_in[19];
    const float* g2n  = (const float*)d_in[20];
    const float* b2n  = (const float*)d_in[21];
    const float* m2n  = (const float*)d_in[22];
    const float* v2n  = (const float*)d_in[23];

    float* out  = (float*)d_out;                         // (B,N,CH) first
    float* edge = out + (size_t)NPTS * CHN;              // then (B,N,K,CH)

    // single kernel: width-detect merged; 8 lanes per point
    gap_kernel<<<(NPTS * 8) / 128, 128>>>(x, idx,
                                    w1, g1, b1, m1, v1, w2, g2, b2, m2, v2,
                                    w1n, g1n, b1n, m1n, v1n, w2n, g2n, b2n, m2n, v2n,
                                    out, edge);
}